// round 8
// baseline (speedup 1.0000x reference)
#include <cuda_runtime.h>
#include <cuda_bf16.h>
#include <math.h>
#include <stdint.h>

// ---------------------------------------------------------------------------
// HPNETLoss — fused kernel with WARP-LEVEL WORK STEALING for the 201 MB
// streaming reduction (fixes cross-SM straggler spread that left DRAM ~30%
// idle with static partitioning).
//   out[0] = sum(weight * (confidence - confidence_gt)^2) / 65536   (16.7M)
//   out[1] = sum(mask * (dr[:,0]-ann[:,0])^2) / N                   (N=8192)
//   out[2] = sum(mask * min(||Mgt-Mp||F, ||Mgt-Mp@RY||F)) / N
// ---------------------------------------------------------------------------

#define BT 256
#define GB 592                 // 148 SMs * 4 blocks
#define TILE4 256u             // float4s per tile per array (4 KB * 3 = 12 KB)
#define KITER 8                // TILE4 / 32 lanes

__device__ float        g_scratch[3];   // self-resetting accumulators
__device__ unsigned int g_count;        // election counter, wraps via atomicInc
__device__ unsigned int g_tile;         // work-stealing counter, reset by elected block

__device__ __forceinline__ float block_reduce(float v, float* warp_sums) {
    int lane = threadIdx.x & 31;
    int wid  = threadIdx.x >> 5;
    #pragma unroll
    for (int off = 16; off > 0; off >>= 1)
        v += __shfl_down_sync(0xFFFFFFFFu, v, off);
    if (lane == 0) warp_sums[wid] = v;
    __syncthreads();
    v = (threadIdx.x < (BT / 32)) ? warp_sums[threadIdx.x] : 0.0f;
    if (wid == 0) {
        #pragma unroll
        for (int off = 16; off > 0; off >>= 1)
            v += __shfl_down_sync(0xFFFFFFFFu, v, off);
    }
    __syncthreads();
    return v;
}

__device__ __forceinline__ void quat2mat(float q0, float q1, float q2, float q3,
                                         float m[9]) {
    m[0] = q0*q0 + q1*q1 - q2*q2 - q3*q3;
    m[1] = 2.0f * (q1*q2 - q0*q3);
    m[2] = 2.0f * (q1*q3 + q0*q2);
    m[3] = 2.0f * (q1*q2 + q0*q3);
    m[4] = q0*q0 - q1*q1 + q2*q2 - q3*q3;
    m[5] = 2.0f * (q2*q3 - q0*q1);
    m[6] = 2.0f * (q1*q3 - q0*q2);
    m[7] = 2.0f * (q2*q3 + q0*q1);
    m[8] = q0*q0 - q1*q1 - q2*q2 + q3*q3;
}

__device__ __forceinline__ float wsq4(float4 w, float4 c, float4 g, float acc) {
    float d0 = c.x - g.x;
    float d1 = c.y - g.y;
    float d2 = c.z - g.z;
    float d3 = c.w - g.w;
    acc = fmaf(w.x * d0, d0, acc);
    acc = fmaf(w.y * d1, d1, acc);
    acc = fmaf(w.z * d2, d2, acc);
    acc = fmaf(w.w * d3, d3, acc);
    return acc;
}

__global__ __launch_bounds__(BT)
void hpnet_loss_ws(const float4* __restrict__ conf,
                   const float4* __restrict__ gt,
                   const float4* __restrict__ wgt,
                   const float*  __restrict__ dr,
                   const float*  __restrict__ ann,
                   const int*    __restrict__ flags,
                   float* __restrict__ out,
                   unsigned n4, int N) {
    __shared__ float warp_sums[BT / 32];

    const int tid  = threadIdx.x;
    const int lane = tid & 31;
    const unsigned gid = blockIdx.x * BT + tid;

    // ---- ann loss (gid < 8192 only; GB*BT = 151,552 covers N in one pass)
    float dpart = 0.0f, rpart = 0.0f;
    if (gid < (unsigned)N) {
        unsigned i = gid;
        if (flags[i] != 0) {
            float dd = dr[i*5 + 0] - ann[i*5 + 0];
            dpart = dd * dd;

            float mp[9];
            quat2mat(ann[i*5+1], ann[i*5+2], ann[i*5+3], ann[i*5+4], mp);

            float q0 = dr[i*5+1], q1 = dr[i*5+2], q2 = dr[i*5+3], q3 = dr[i*5+4];
            float inv = rsqrtf(q0*q0 + q1*q1 + q2*q2 + q3*q3);
            float mg[9];
            quat2mat(q0*inv, q1*inv, q2*inv, q3*inv, mg);

            // RY = diag(-1,1,-1): columns 0,2 of mp negated for the second norm
            float s1 = 0.0f, s2 = 0.0f;
            #pragma unroll
            for (int r = 0; r < 3; ++r) {
                float e0 = mg[r*3+0] - mp[r*3+0];
                float e1 = mg[r*3+1] - mp[r*3+1];
                float e2 = mg[r*3+2] - mp[r*3+2];
                s1 += e0*e0 + e1*e1 + e2*e2;
                float f0 = mg[r*3+0] + mp[r*3+0];
                float f1 = mg[r*3+1] - mp[r*3+1];
                float f2 = mg[r*3+2] + mp[r*3+2];
                s2 += f0*f0 + f1*f1 + f2*f2;
            }
            rpart = sqrtf(fminf(s1, s2));
        }
    }

    // ---- confidence loss: warp-level work stealing over 12 KB tiles
    const unsigned ntiles = n4 / TILE4;    // 16384 for the given shape

    float acc = 0.0f;
    unsigned ticket = 0;
    if (lane == 0) ticket = atomicAdd(&g_tile, 1u);
    ticket = __shfl_sync(0xFFFFFFFFu, ticket, 0);

    while (ticket < ntiles) {
        // prefetch next ticket so ATOMG latency hides under the tile's loads
        unsigned nxt = 0;
        if (lane == 0) nxt = atomicAdd(&g_tile, 1u);

        unsigned base = ticket * TILE4 + (unsigned)lane;
        #pragma unroll
        for (int k = 0; k < KITER; ++k) {
            unsigned idx = base + (unsigned)(k * 32);
            acc = wsq4(wgt[idx], conf[idx], gt[idx], acc);
        }

        nxt = __shfl_sync(0xFFFFFFFFu, nxt, 0);
        ticket = nxt;
    }

    // remainder (n4 not multiple of TILE4): block 0 handles it
    unsigned rem_start = ntiles * TILE4;
    if (blockIdx.x == 0) {
        for (unsigned i = rem_start + tid; i < n4; i += BT) {
            acc = wsq4(wgt[i], conf[i], gt[i], acc);
        }
    }

    // ---- block reductions + completion / self-reset
    float csum = block_reduce(acc,   warp_sums);
    float dsum = block_reduce(dpart, warp_sums);
    float rsum = block_reduce(rpart, warp_sums);

    if (tid == 0) {
        if (csum != 0.0f) atomicAdd(&g_scratch[0], csum);
        if (dsum != 0.0f) atomicAdd(&g_scratch[1], dsum);
        if (rsum != 0.0f) atomicAdd(&g_scratch[2], rsum);
        __threadfence();
        unsigned int t = atomicInc(&g_count, GB - 1);
        if (t == GB - 1) {
            // last block: read+reset scratch and tile counter, write outputs
            float s0 = atomicExch(&g_scratch[0], 0.0f);
            float s1 = atomicExch(&g_scratch[1], 0.0f);
            float s2 = atomicExch(&g_scratch[2], 0.0f);
            atomicExch(&g_tile, 0u);
            float invN = 1.0f / (float)N;
            out[0] = s0 * (1.0f / 65536.0f);
            out[1] = s1 * invN;
            out[2] = s2 * invN;
        }
    }
}

extern "C" void kernel_launch(void* const* d_in, const int* in_sizes, int n_in,
                              void* d_out, int out_size) {
    const float* conf = (const float*)d_in[0];
    const float* gt   = (const float*)d_in[1];
    const float* wgt  = (const float*)d_in[2];
    const float* dr   = (const float*)d_in[3];
    const float* ann  = (const float*)d_in[4];
    const int*   flags = (const int*)d_in[5];
    float* out = (float*)d_out;

    unsigned n4 = (unsigned)(in_sizes[0] / 4);   // 4,194,304 float4s
    int N = in_sizes[5];                         // 8192

    hpnet_loss_ws<<<GB, BT>>>(
        (const float4*)conf, (const float4*)gt, (const float4*)wgt,
        dr, ann, flags, out, n4, N);
}

// round 9
// speedup vs baseline: 1.1319x; 1.1319x over previous
#include <cuda_runtime.h>
#include <cuda_bf16.h>
#include <math.h>

// ---------------------------------------------------------------------------
// HPNETLoss — single fused kernel (R3 structure, best measured) with
// ld.global.nc.L2::256B streaming loads: 256B L2 fetch granularity pairs
// adjacent lines per DRAM access for better row locality.
//   out[0] = sum(weight * (confidence - confidence_gt)^2) / 65536   (16.7M)
//   out[1] = sum(mask * (dr[:,0]-ann[:,0])^2) / N                   (N=8192)
//   out[2] = sum(mask * min(||Mgt-Mp||F, ||Mgt-Mp@RY||F)) / N
// ---------------------------------------------------------------------------

#define BT 256
#define GB 1184           // 148 SMs * 8 blocks

__device__ float        g_scratch[3];   // self-resetting accumulators
__device__ unsigned int g_count;        // wraps to 0 via atomicInc

__device__ __forceinline__ float4 ldg_nc_256(const float4* p) {
    float4 v;
    asm("ld.global.nc.L2::256B.v4.f32 {%0,%1,%2,%3}, [%4];"
        : "=f"(v.x), "=f"(v.y), "=f"(v.z), "=f"(v.w) : "l"(p));
    return v;
}

__device__ __forceinline__ float block_reduce(float v, float* warp_sums) {
    int lane = threadIdx.x & 31;
    int wid  = threadIdx.x >> 5;
    #pragma unroll
    for (int off = 16; off > 0; off >>= 1)
        v += __shfl_down_sync(0xFFFFFFFFu, v, off);
    if (lane == 0) warp_sums[wid] = v;
    __syncthreads();
    v = (threadIdx.x < (BT / 32)) ? warp_sums[threadIdx.x] : 0.0f;
    if (wid == 0) {
        #pragma unroll
        for (int off = 16; off > 0; off >>= 1)
            v += __shfl_down_sync(0xFFFFFFFFu, v, off);
    }
    __syncthreads();
    return v;
}

__device__ __forceinline__ void quat2mat(float q0, float q1, float q2, float q3,
                                         float m[9]) {
    m[0] = q0*q0 + q1*q1 - q2*q2 - q3*q3;
    m[1] = 2.0f * (q1*q2 - q0*q3);
    m[2] = 2.0f * (q1*q3 + q0*q2);
    m[3] = 2.0f * (q1*q2 + q0*q3);
    m[4] = q0*q0 - q1*q1 + q2*q2 - q3*q3;
    m[5] = 2.0f * (q2*q3 - q0*q1);
    m[6] = 2.0f * (q1*q3 - q0*q2);
    m[7] = 2.0f * (q2*q3 + q0*q1);
    m[8] = q0*q0 - q1*q1 - q2*q2 + q3*q3;
}

__device__ __forceinline__ float wsq4(float4 w, float4 c, float4 g, float acc) {
    float d0 = c.x - g.x;
    float d1 = c.y - g.y;
    float d2 = c.z - g.z;
    float d3 = c.w - g.w;
    acc = fmaf(w.x * d0, d0, acc);
    acc = fmaf(w.y * d1, d1, acc);
    acc = fmaf(w.z * d2, d2, acc);
    acc = fmaf(w.w * d3, d3, acc);
    return acc;
}

__global__ __launch_bounds__(BT)
void hpnet_loss_fused(const float4* __restrict__ conf,
                      const float4* __restrict__ gt,
                      const float4* __restrict__ wgt,
                      const float*  __restrict__ dr,
                      const float*  __restrict__ ann,
                      const int*    __restrict__ flags,
                      float* __restrict__ out,
                      long n4, int N) {
    __shared__ float warp_sums[BT / 32];

    const long gid    = (long)blockIdx.x * BT + threadIdx.x;
    const long stride = (long)GB * BT;

    // ---- ann loss (gid < 8192 only; hidden under the stream)
    float dpart = 0.0f, rpart = 0.0f;
    for (long i = gid; i < N; i += stride) {
        if (flags[i] != 0) {
            float dd = dr[i*5 + 0] - ann[i*5 + 0];
            dpart += dd * dd;

            float mp[9];
            quat2mat(ann[i*5+1], ann[i*5+2], ann[i*5+3], ann[i*5+4], mp);

            float q0 = dr[i*5+1], q1 = dr[i*5+2], q2 = dr[i*5+3], q3 = dr[i*5+4];
            float inv = rsqrtf(q0*q0 + q1*q1 + q2*q2 + q3*q3);
            float mg[9];
            quat2mat(q0*inv, q1*inv, q2*inv, q3*inv, mg);

            // RY = diag(-1,1,-1): columns 0,2 of mp negated for the second norm
            float s1 = 0.0f, s2 = 0.0f;
            #pragma unroll
            for (int r = 0; r < 3; ++r) {
                float e0 = mg[r*3+0] - mp[r*3+0];
                float e1 = mg[r*3+1] - mp[r*3+1];
                float e2 = mg[r*3+2] - mp[r*3+2];
                s1 += e0*e0 + e1*e1 + e2*e2;
                float f0 = mg[r*3+0] + mp[r*3+0];
                float f1 = mg[r*3+1] - mp[r*3+1];
                float f2 = mg[r*3+2] + mp[r*3+2];
                s2 += f0*f0 + f1*f1 + f2*f2;
            }
            rpart += sqrtf(fminf(s1, s2));
        }
    }

    // ---- confidence loss: streaming float4 reduction, 256B L2 granularity
    float acc = 0.0f;
    #pragma unroll 4
    for (long i = gid; i < n4; i += stride) {
        float4 c = ldg_nc_256(&conf[i]);
        float4 g = ldg_nc_256(&gt[i]);
        float4 w = ldg_nc_256(&wgt[i]);
        acc = wsq4(w, c, g, acc);
    }

    // ---- block reductions + completion / self-reset
    float csum = block_reduce(acc,   warp_sums);
    float dsum = block_reduce(dpart, warp_sums);
    float rsum = block_reduce(rpart, warp_sums);

    if (threadIdx.x == 0) {
        if (csum != 0.0f) atomicAdd(&g_scratch[0], csum);
        if (dsum != 0.0f) atomicAdd(&g_scratch[1], dsum);
        if (rsum != 0.0f) atomicAdd(&g_scratch[2], rsum);
        __threadfence();
        unsigned int ticket = atomicInc(&g_count, GB - 1);
        if (ticket == GB - 1) {
            float s0 = atomicExch(&g_scratch[0], 0.0f);
            float s1 = atomicExch(&g_scratch[1], 0.0f);
            float s2 = atomicExch(&g_scratch[2], 0.0f);
            float invN = 1.0f / (float)N;
            out[0] = s0 * (1.0f / 65536.0f);
            out[1] = s1 * invN;
            out[2] = s2 * invN;
        }
    }
}

extern "C" void kernel_launch(void* const* d_in, const int* in_sizes, int n_in,
                              void* d_out, int out_size) {
    const float* conf = (const float*)d_in[0];
    const float* gt   = (const float*)d_in[1];
    const float* wgt  = (const float*)d_in[2];
    const float* dr   = (const float*)d_in[3];
    const float* ann  = (const float*)d_in[4];
    const int*   flags = (const int*)d_in[5];
    float* out = (float*)d_out;

    long n4 = (long)in_sizes[0] / 4;   // 4,194,304 float4s
    int  N  = in_sizes[5];             // 8192

    hpnet_loss_fused<<<GB, BT>>>(
        (const float4*)conf, (const float4*)gt, (const float4*)wgt,
        dr, ann, flags, out, n4, N);
}

// round 10
// speedup vs baseline: 1.1739x; 1.0371x over previous
#include <cuda_runtime.h>
#include <cuda_bf16.h>
#include <math.h>
#include <stdint.h>

// ---------------------------------------------------------------------------
// HPNETLoss — fused kernel. Streaming loads: ld.global.nc with L2::256B fetch
// granularity + evict_first L2 policy. One-wave grid (888 = 148 SMs x 6).
//   out[0] = sum(weight * (confidence - confidence_gt)^2) / 65536   (16.7M)
//   out[1] = sum(mask * (dr[:,0]-ann[:,0])^2) / N                   (N=8192)
//   out[2] = sum(mask * min(||Mgt-Mp||F, ||Mgt-Mp@RY||F)) / N
// ---------------------------------------------------------------------------

#define BT 256
#define GB 888            // 148 SMs * 6 blocks = exactly one resident wave

__device__ float        g_scratch[3];   // self-resetting accumulators
__device__ unsigned int g_count;        // wraps to 0 via atomicInc

__device__ __forceinline__ uint64_t mk_policy() {
    uint64_t pol;
    asm("createpolicy.fractional.L2::evict_first.b64 %0, 1.0;" : "=l"(pol));
    return pol;
}

__device__ __forceinline__ float4 ldg_stream(const float4* p, uint64_t pol) {
    float4 v;
    asm("ld.global.nc.L2::cache_hint.L2::256B.v4.f32 {%0,%1,%2,%3}, [%4], %5;"
        : "=f"(v.x), "=f"(v.y), "=f"(v.z), "=f"(v.w) : "l"(p), "l"(pol));
    return v;
}

__device__ __forceinline__ float block_reduce(float v, float* warp_sums) {
    int lane = threadIdx.x & 31;
    int wid  = threadIdx.x >> 5;
    #pragma unroll
    for (int off = 16; off > 0; off >>= 1)
        v += __shfl_down_sync(0xFFFFFFFFu, v, off);
    if (lane == 0) warp_sums[wid] = v;
    __syncthreads();
    v = (threadIdx.x < (BT / 32)) ? warp_sums[threadIdx.x] : 0.0f;
    if (wid == 0) {
        #pragma unroll
        for (int off = 16; off > 0; off >>= 1)
            v += __shfl_down_sync(0xFFFFFFFFu, v, off);
    }
    __syncthreads();
    return v;
}

__device__ __forceinline__ void quat2mat(float q0, float q1, float q2, float q3,
                                         float m[9]) {
    m[0] = q0*q0 + q1*q1 - q2*q2 - q3*q3;
    m[1] = 2.0f * (q1*q2 - q0*q3);
    m[2] = 2.0f * (q1*q3 + q0*q2);
    m[3] = 2.0f * (q1*q2 + q0*q3);
    m[4] = q0*q0 - q1*q1 + q2*q2 - q3*q3;
    m[5] = 2.0f * (q2*q3 - q0*q1);
    m[6] = 2.0f * (q1*q3 - q0*q2);
    m[7] = 2.0f * (q2*q3 + q0*q1);
    m[8] = q0*q0 - q1*q1 - q2*q2 + q3*q3;
}

__device__ __forceinline__ float wsq4(float4 w, float4 c, float4 g, float acc) {
    float d0 = c.x - g.x;
    float d1 = c.y - g.y;
    float d2 = c.z - g.z;
    float d3 = c.w - g.w;
    acc = fmaf(w.x * d0, d0, acc);
    acc = fmaf(w.y * d1, d1, acc);
    acc = fmaf(w.z * d2, d2, acc);
    acc = fmaf(w.w * d3, d3, acc);
    return acc;
}

__global__ __launch_bounds__(BT, 6)
void hpnet_loss_fused(const float4* __restrict__ conf,
                      const float4* __restrict__ gt,
                      const float4* __restrict__ wgt,
                      const float*  __restrict__ dr,
                      const float*  __restrict__ ann,
                      const int*    __restrict__ flags,
                      float* __restrict__ out,
                      unsigned n4, int N) {
    __shared__ float warp_sums[BT / 32];

    const unsigned gid    = blockIdx.x * BT + threadIdx.x;
    const unsigned stride = GB * BT;     // 227,328

    // ---- ann loss (gid < 8192 only; hidden under the stream)
    float dpart = 0.0f, rpart = 0.0f;
    if (gid < (unsigned)N) {
        unsigned i = gid;
        if (flags[i] != 0) {
            float dd = dr[i*5 + 0] - ann[i*5 + 0];
            dpart = dd * dd;

            float mp[9];
            quat2mat(ann[i*5+1], ann[i*5+2], ann[i*5+3], ann[i*5+4], mp);

            float q0 = dr[i*5+1], q1 = dr[i*5+2], q2 = dr[i*5+3], q3 = dr[i*5+4];
            float inv = rsqrtf(q0*q0 + q1*q1 + q2*q2 + q3*q3);
            float mg[9];
            quat2mat(q0*inv, q1*inv, q2*inv, q3*inv, mg);

            // RY = diag(-1,1,-1): columns 0,2 of mp negated for the second norm
            float s1 = 0.0f, s2 = 0.0f;
            #pragma unroll
            for (int r = 0; r < 3; ++r) {
                float e0 = mg[r*3+0] - mp[r*3+0];
                float e1 = mg[r*3+1] - mp[r*3+1];
                float e2 = mg[r*3+2] - mp[r*3+2];
                s1 += e0*e0 + e1*e1 + e2*e2;
                float f0 = mg[r*3+0] + mp[r*3+0];
                float f1 = mg[r*3+1] - mp[r*3+1];
                float f2 = mg[r*3+2] + mp[r*3+2];
                s2 += f0*f0 + f1*f1 + f2*f2;
            }
            rpart = sqrtf(fminf(s1, s2));
        }
    }

    // ---- confidence loss: one-wave grid-stride, 256B + evict_first loads
    const uint64_t pol = mk_policy();
    float acc = 0.0f;
    #pragma unroll 4
    for (unsigned i = gid; i < n4; i += stride) {
        float4 c = ldg_stream(&conf[i], pol);
        float4 g = ldg_stream(&gt[i],   pol);
        float4 w = ldg_stream(&wgt[i],  pol);
        acc = wsq4(w, c, g, acc);
    }

    // ---- block reductions + completion / self-reset
    float csum = block_reduce(acc,   warp_sums);
    float dsum = block_reduce(dpart, warp_sums);
    float rsum = block_reduce(rpart, warp_sums);

    if (threadIdx.x == 0) {
        if (csum != 0.0f) atomicAdd(&g_scratch[0], csum);
        if (dsum != 0.0f) atomicAdd(&g_scratch[1], dsum);
        if (rsum != 0.0f) atomicAdd(&g_scratch[2], rsum);
        __threadfence();
        unsigned int ticket = atomicInc(&g_count, GB - 1);
        if (ticket == GB - 1) {
            float s0 = atomicExch(&g_scratch[0], 0.0f);
            float s1 = atomicExch(&g_scratch[1], 0.0f);
            float s2 = atomicExch(&g_scratch[2], 0.0f);
            float invN = 1.0f / (float)N;
            out[0] = s0 * (1.0f / 65536.0f);
            out[1] = s1 * invN;
            out[2] = s2 * invN;
        }
    }
}

extern "C" void kernel_launch(void* const* d_in, const int* in_sizes, int n_in,
                              void* d_out, int out_size) {
    const float* conf = (const float*)d_in[0];
    const float* gt   = (const float*)d_in[1];
    const float* wgt  = (const float*)d_in[2];
    const float* dr   = (const float*)d_in[3];
    const float* ann  = (const float*)d_in[4];
    const int*   flags = (const int*)d_in[5];
    float* out = (float*)d_out;

    unsigned n4 = (unsigned)(in_sizes[0] / 4);   // 4,194,304 float4s
    int N = in_sizes[5];                         // 8192

    hpnet_loss_fused<<<GB, BT>>>(
        (const float4*)conf, (const float4*)gt, (const float4*)wgt,
        dr, ann, flags, out, n4, N);
}

// round 11
// speedup vs baseline: 1.4087x; 1.2000x over previous
#include <cuda_runtime.h>
#include <cuda_bf16.h>
#include <math.h>
#include <stdint.h>

// ---------------------------------------------------------------------------
// HPNETLoss — fused kernel. Streaming loads: ld.global.nc L2::256B +
// evict_first policy, one-wave grid (888 = 148 x 6), plus an explicit
// prefetch.global.L2 stream 2 grid-strides ahead to decouple DRAM reads
// from the warp dependency chain.
//   out[0] = sum(weight * (confidence - confidence_gt)^2) / 65536   (16.7M)
//   out[1] = sum(mask * (dr[:,0]-ann[:,0])^2) / N                   (N=8192)
//   out[2] = sum(mask * min(||Mgt-Mp||F, ||Mgt-Mp@RY||F)) / N
// ---------------------------------------------------------------------------

#define BT 256
#define GB 888            // 148 SMs * 6 blocks = exactly one resident wave
#define PF_DIST 2u        // prefetch lookahead in grid-strides (~7 MB / ~1.2 us)

__device__ float        g_scratch[3];   // self-resetting accumulators
__device__ unsigned int g_count;        // wraps to 0 via atomicInc

__device__ __forceinline__ uint64_t mk_policy() {
    uint64_t pol;
    asm("createpolicy.fractional.L2::evict_first.b64 %0, 1.0;" : "=l"(pol));
    return pol;
}

__device__ __forceinline__ float4 ldg_stream(const float4* p, uint64_t pol) {
    float4 v;
    asm("ld.global.nc.L2::cache_hint.L2::256B.v4.f32 {%0,%1,%2,%3}, [%4], %5;"
        : "=f"(v.x), "=f"(v.y), "=f"(v.z), "=f"(v.w) : "l"(p), "l"(pol));
    return v;
}

__device__ __forceinline__ void pf_l2(const float4* p) {
    asm volatile("prefetch.global.L2 [%0];" :: "l"(p));
}

__device__ __forceinline__ float block_reduce(float v, float* warp_sums) {
    int lane = threadIdx.x & 31;
    int wid  = threadIdx.x >> 5;
    #pragma unroll
    for (int off = 16; off > 0; off >>= 1)
        v += __shfl_down_sync(0xFFFFFFFFu, v, off);
    if (lane == 0) warp_sums[wid] = v;
    __syncthreads();
    v = (threadIdx.x < (BT / 32)) ? warp_sums[threadIdx.x] : 0.0f;
    if (wid == 0) {
        #pragma unroll
        for (int off = 16; off > 0; off >>= 1)
            v += __shfl_down_sync(0xFFFFFFFFu, v, off);
    }
    __syncthreads();
    return v;
}

__device__ __forceinline__ void quat2mat(float q0, float q1, float q2, float q3,
                                         float m[9]) {
    m[0] = q0*q0 + q1*q1 - q2*q2 - q3*q3;
    m[1] = 2.0f * (q1*q2 - q0*q3);
    m[2] = 2.0f * (q1*q3 + q0*q2);
    m[3] = 2.0f * (q1*q2 + q0*q3);
    m[4] = q0*q0 - q1*q1 + q2*q2 - q3*q3;
    m[5] = 2.0f * (q2*q3 - q0*q1);
    m[6] = 2.0f * (q1*q3 - q0*q2);
    m[7] = 2.0f * (q2*q3 + q0*q1);
    m[8] = q0*q0 - q1*q1 - q2*q2 + q3*q3;
}

__device__ __forceinline__ float wsq4(float4 w, float4 c, float4 g, float acc) {
    float d0 = c.x - g.x;
    float d1 = c.y - g.y;
    float d2 = c.z - g.z;
    float d3 = c.w - g.w;
    acc = fmaf(w.x * d0, d0, acc);
    acc = fmaf(w.y * d1, d1, acc);
    acc = fmaf(w.z * d2, d2, acc);
    acc = fmaf(w.w * d3, d3, acc);
    return acc;
}

__global__ __launch_bounds__(BT, 6)
void hpnet_loss_fused(const float4* __restrict__ conf,
                      const float4* __restrict__ gt,
                      const float4* __restrict__ wgt,
                      const float*  __restrict__ dr,
                      const float*  __restrict__ ann,
                      const int*    __restrict__ flags,
                      float* __restrict__ out,
                      unsigned n4, int N) {
    __shared__ float warp_sums[BT / 32];

    const unsigned gid    = blockIdx.x * BT + threadIdx.x;
    const unsigned stride = GB * BT;     // 227,328

    // ---- ann loss (gid < 8192 only; hidden under the stream)
    float dpart = 0.0f, rpart = 0.0f;
    if (gid < (unsigned)N) {
        unsigned i = gid;
        if (flags[i] != 0) {
            float dd = dr[i*5 + 0] - ann[i*5 + 0];
            dpart = dd * dd;

            float mp[9];
            quat2mat(ann[i*5+1], ann[i*5+2], ann[i*5+3], ann[i*5+4], mp);

            float q0 = dr[i*5+1], q1 = dr[i*5+2], q2 = dr[i*5+3], q3 = dr[i*5+4];
            float inv = rsqrtf(q0*q0 + q1*q1 + q2*q2 + q3*q3);
            float mg[9];
            quat2mat(q0*inv, q1*inv, q2*inv, q3*inv, mg);

            // RY = diag(-1,1,-1): columns 0,2 of mp negated for the second norm
            float s1 = 0.0f, s2 = 0.0f;
            #pragma unroll
            for (int r = 0; r < 3; ++r) {
                float e0 = mg[r*3+0] - mp[r*3+0];
                float e1 = mg[r*3+1] - mp[r*3+1];
                float e2 = mg[r*3+2] - mp[r*3+2];
                s1 += e0*e0 + e1*e1 + e2*e2;
                float f0 = mg[r*3+0] + mp[r*3+0];
                float f1 = mg[r*3+1] - mp[r*3+1];
                float f2 = mg[r*3+2] + mp[r*3+2];
                s2 += f0*f0 + f1*f1 + f2*f2;
            }
            rpart = sqrtf(fminf(s1, s2));
        }
    }

    // ---- confidence loss: one-wave grid-stride; demand loads with 256B +
    //      evict_first; explicit L2 prefetch stream PF_DIST strides ahead
    const uint64_t pol = mk_policy();
    float acc = 0.0f;
    #pragma unroll 4
    for (unsigned i = gid; i < n4; i += stride) {
        unsigned ip = i + PF_DIST * stride;
        if (ip < n4) {
            pf_l2(&conf[ip]);
            pf_l2(&gt[ip]);
            pf_l2(&wgt[ip]);
        }
        float4 c = ldg_stream(&conf[i], pol);
        float4 g = ldg_stream(&gt[i],   pol);
        float4 w = ldg_stream(&wgt[i],  pol);
        acc = wsq4(w, c, g, acc);
    }

    // ---- block reductions + completion / self-reset
    float csum = block_reduce(acc,   warp_sums);
    float dsum = block_reduce(dpart, warp_sums);
    float rsum = block_reduce(rpart, warp_sums);

    if (threadIdx.x == 0) {
        if (csum != 0.0f) atomicAdd(&g_scratch[0], csum);
        if (dsum != 0.0f) atomicAdd(&g_scratch[1], dsum);
        if (rsum != 0.0f) atomicAdd(&g_scratch[2], rsum);
        __threadfence();
        unsigned int ticket = atomicInc(&g_count, GB - 1);
        if (ticket == GB - 1) {
            float s0 = atomicExch(&g_scratch[0], 0.0f);
            float s1 = atomicExch(&g_scratch[1], 0.0f);
            float s2 = atomicExch(&g_scratch[2], 0.0f);
            float invN = 1.0f / (float)N;
            out[0] = s0 * (1.0f / 65536.0f);
            out[1] = s1 * invN;
            out[2] = s2 * invN;
        }
    }
}

extern "C" void kernel_launch(void* const* d_in, const int* in_sizes, int n_in,
                              void* d_out, int out_size) {
    const float* conf = (const float*)d_in[0];
    const float* gt   = (const float*)d_in[1];
    const float* wgt  = (const float*)d_in[2];
    const float* dr   = (const float*)d_in[3];
    const float* ann  = (const float*)d_in[4];
    const int*   flags = (const int*)d_in[5];
    float* out = (float*)d_out;

    unsigned n4 = (unsigned)(in_sizes[0] / 4);   // 4,194,304 float4s
    int N = in_sizes[5];                         // 8192

    hpnet_loss_fused<<<GB, BT>>>(
        (const float4*)conf, (const float4*)gt, (const float4*)wgt,
        dr, ann, flags, out, n4, N);
}

// round 12
// speedup vs baseline: 1.4448x; 1.0256x over previous
#include <cuda_runtime.h>
#include <cuda_bf16.h>
#include <math.h>
#include <stdint.h>

// ---------------------------------------------------------------------------
// HPNETLoss — fused kernel. Streaming loads: ld.global.nc L2::256B +
// evict_first policy, one-wave grid (888 = 148 x 6), plus an explicit
// prefetch.global.L2 stream 2 grid-strides ahead to decouple DRAM reads
// from the warp dependency chain.
//   out[0] = sum(weight * (confidence - confidence_gt)^2) / 65536   (16.7M)
//   out[1] = sum(mask * (dr[:,0]-ann[:,0])^2) / N                   (N=8192)
//   out[2] = sum(mask * min(||Mgt-Mp||F, ||Mgt-Mp@RY||F)) / N
// ---------------------------------------------------------------------------

#define BT 256
#define GB 888            // 148 SMs * 6 blocks = exactly one resident wave
#define PF_DIST 2u        // prefetch lookahead in grid-strides (~7 MB / ~1.2 us)

__device__ float        g_scratch[3];   // self-resetting accumulators
__device__ unsigned int g_count;        // wraps to 0 via atomicInc

__device__ __forceinline__ uint64_t mk_policy() {
    uint64_t pol;
    asm("createpolicy.fractional.L2::evict_first.b64 %0, 1.0;" : "=l"(pol));
    return pol;
}

__device__ __forceinline__ float4 ldg_stream(const float4* p, uint64_t pol) {
    float4 v;
    asm("ld.global.nc.L2::cache_hint.L2::256B.v4.f32 {%0,%1,%2,%3}, [%4], %5;"
        : "=f"(v.x), "=f"(v.y), "=f"(v.z), "=f"(v.w) : "l"(p), "l"(pol));
    return v;
}

__device__ __forceinline__ void pf_l2(const float4* p) {
    asm volatile("prefetch.global.L2 [%0];" :: "l"(p));
}

__device__ __forceinline__ float block_reduce(float v, float* warp_sums) {
    int lane = threadIdx.x & 31;
    int wid  = threadIdx.x >> 5;
    #pragma unroll
    for (int off = 16; off > 0; off >>= 1)
        v += __shfl_down_sync(0xFFFFFFFFu, v, off);
    if (lane == 0) warp_sums[wid] = v;
    __syncthreads();
    v = (threadIdx.x < (BT / 32)) ? warp_sums[threadIdx.x] : 0.0f;
    if (wid == 0) {
        #pragma unroll
        for (int off = 16; off > 0; off >>= 1)
            v += __shfl_down_sync(0xFFFFFFFFu, v, off);
    }
    __syncthreads();
    return v;
}

__device__ __forceinline__ void quat2mat(float q0, float q1, float q2, float q3,
                                         float m[9]) {
    m[0] = q0*q0 + q1*q1 - q2*q2 - q3*q3;
    m[1] = 2.0f * (q1*q2 - q0*q3);
    m[2] = 2.0f * (q1*q3 + q0*q2);
    m[3] = 2.0f * (q1*q2 + q0*q3);
    m[4] = q0*q0 - q1*q1 + q2*q2 - q3*q3;
    m[5] = 2.0f * (q2*q3 - q0*q1);
    m[6] = 2.0f * (q1*q3 - q0*q2);
    m[7] = 2.0f * (q2*q3 + q0*q1);
    m[8] = q0*q0 - q1*q1 - q2*q2 + q3*q3;
}

__device__ __forceinline__ float wsq4(float4 w, float4 c, float4 g, float acc) {
    float d0 = c.x - g.x;
    float d1 = c.y - g.y;
    float d2 = c.z - g.z;
    float d3 = c.w - g.w;
    acc = fmaf(w.x * d0, d0, acc);
    acc = fmaf(w.y * d1, d1, acc);
    acc = fmaf(w.z * d2, d2, acc);
    acc = fmaf(w.w * d3, d3, acc);
    return acc;
}

__global__ __launch_bounds__(BT, 6)
void hpnet_loss_fused(const float4* __restrict__ conf,
                      const float4* __restrict__ gt,
                      const float4* __restrict__ wgt,
                      const float*  __restrict__ dr,
                      const float*  __restrict__ ann,
                      const int*    __restrict__ flags,
                      float* __restrict__ out,
                      unsigned n4, int N) {
    __shared__ float warp_sums[BT / 32];

    const unsigned gid    = blockIdx.x * BT + threadIdx.x;
    const unsigned stride = GB * BT;     // 227,328

    // ---- ann loss (gid < 8192 only; hidden under the stream)
    float dpart = 0.0f, rpart = 0.0f;
    if (gid < (unsigned)N) {
        unsigned i = gid;
        if (flags[i] != 0) {
            float dd = dr[i*5 + 0] - ann[i*5 + 0];
            dpart = dd * dd;

            float mp[9];
            quat2mat(ann[i*5+1], ann[i*5+2], ann[i*5+3], ann[i*5+4], mp);

            float q0 = dr[i*5+1], q1 = dr[i*5+2], q2 = dr[i*5+3], q3 = dr[i*5+4];
            float inv = rsqrtf(q0*q0 + q1*q1 + q2*q2 + q3*q3);
            float mg[9];
            quat2mat(q0*inv, q1*inv, q2*inv, q3*inv, mg);

            // RY = diag(-1,1,-1): columns 0,2 of mp negated for the second norm
            float s1 = 0.0f, s2 = 0.0f;
            #pragma unroll
            for (int r = 0; r < 3; ++r) {
                float e0 = mg[r*3+0] - mp[r*3+0];
                float e1 = mg[r*3+1] - mp[r*3+1];
                float e2 = mg[r*3+2] - mp[r*3+2];
                s1 += e0*e0 + e1*e1 + e2*e2;
                float f0 = mg[r*3+0] + mp[r*3+0];
                float f1 = mg[r*3+1] - mp[r*3+1];
                float f2 = mg[r*3+2] + mp[r*3+2];
                s2 += f0*f0 + f1*f1 + f2*f2;
            }
            rpart = sqrtf(fminf(s1, s2));
        }
    }

    // ---- confidence loss: one-wave grid-stride; demand loads with 256B +
    //      evict_first; explicit L2 prefetch stream PF_DIST strides ahead
    const uint64_t pol = mk_policy();
    float acc = 0.0f;
    #pragma unroll 4
    for (unsigned i = gid; i < n4; i += stride) {
        unsigned ip = i + PF_DIST * stride;
        if (ip < n4) {
            pf_l2(&conf[ip]);
            pf_l2(&gt[ip]);
            pf_l2(&wgt[ip]);
        }
        float4 c = ldg_stream(&conf[i], pol);
        float4 g = ldg_stream(&gt[i],   pol);
        float4 w = ldg_stream(&wgt[i],  pol);
        acc = wsq4(w, c, g, acc);
    }

    // ---- block reductions + completion / self-reset
    float csum = block_reduce(acc,   warp_sums);
    float dsum = block_reduce(dpart, warp_sums);
    float rsum = block_reduce(rpart, warp_sums);

    if (threadIdx.x == 0) {
        if (csum != 0.0f) atomicAdd(&g_scratch[0], csum);
        if (dsum != 0.0f) atomicAdd(&g_scratch[1], dsum);
        if (rsum != 0.0f) atomicAdd(&g_scratch[2], rsum);
        __threadfence();
        unsigned int ticket = atomicInc(&g_count, GB - 1);
        if (ticket == GB - 1) {
            float s0 = atomicExch(&g_scratch[0], 0.0f);
            float s1 = atomicExch(&g_scratch[1], 0.0f);
            float s2 = atomicExch(&g_scratch[2], 0.0f);
            float invN = 1.0f / (float)N;
            out[0] = s0 * (1.0f / 65536.0f);
            out[1] = s1 * invN;
            out[2] = s2 * invN;
        }
    }
}

extern "C" void kernel_launch(void* const* d_in, const int* in_sizes, int n_in,
                              void* d_out, int out_size) {
    const float* conf = (const float*)d_in[0];
    const float* gt   = (const float*)d_in[1];
    const float* wgt  = (const float*)d_in[2];
    const float* dr   = (const float*)d_in[3];
    const float* ann  = (const float*)d_in[4];
    const int*   flags = (const int*)d_in[5];
    float* out = (float*)d_out;

    unsigned n4 = (unsigned)(in_sizes[0] / 4);   // 4,194,304 float4s
    int N = in_sizes[5];                         // 8192

    hpnet_loss_fused<<<GB, BT>>>(
        (const float4*)conf, (const float4*)gt, (const float4*)wgt,
        dr, ann, flags, out, n4, N);
}